// round 1
// baseline (speedup 1.0000x reference)
#include <cuda_runtime.h>

// out[q] = sum_{k<=q} (Q_q . K_k)^2 V_k / (sum_{k<=q} (Q_q . K_k)^2 + EPS)
// Exact algebraic collapse of the chunked reference (see analysis).
// Shapes fixed by the problem: b=2, t=2048, h=8, d=dv=64.

constexpr int B_ = 2;
constexpr int T_ = 2048;
constexpr int H_ = 8;
constexpr int D_ = 64;
constexpr int BM = 64;
constexpr int BN = 64;
constexpr float EPSF = 1e-5f;

__global__ __launch_bounds__(256, 2)
void attn_pow2_kernel(const float* __restrict__ Qg,
                      const float* __restrict__ Kg,
                      const float* __restrict__ Vg,
                      float* __restrict__ Og)
{
    __shared__ __align__(16) float Qs[D_][BM];      // transposed: Qs[d][q]
    __shared__ __align__(16) float Ks[D_][BN];      // transposed: Ks[d][k]
    __shared__ __align__(16) float Vs[BN][D_];      // Vs[k][v]
    __shared__ __align__(16) float Ss[BM][BN];      // squared+masked scores, row-major
    __shared__ float Zs[BM];

    // Reverse q-tile order: largest-work blocks launch first (triangular balance).
    const int qt  = (int)(gridDim.x - 1 - blockIdx.x);
    const int bh  = (int)blockIdx.y;
    const int bb  = bh >> 3;
    const int hh  = bh & 7;
    const int tid = (int)threadIdx.x;
    const int tx  = tid & 15;      // 16 cols of threads
    const int ty  = tid >> 4;      // 16 rows of threads
    const int q0  = ty * 4;        // this thread's 4 query rows
    const int c0  = tx * 4;        // this thread's 4 key/value cols

    const size_t headoff  = ((size_t)bb * T_ * H_ + hh) * D_;
    const int    rowstride = H_ * D_;   // 512 floats between consecutive tokens

    // ---- load Q tile (transposed into smem) ----
    const int qbase = qt * BM;
    for (int i = tid; i < BM * (D_ / 4); i += 256) {
        int r  = i >> 4;            // token row within tile
        int c4 = (i & 15) * 4;      // feature col (multiple of 4)
        float4 v = *(const float4*)(Qg + headoff + (size_t)(qbase + r) * rowstride + c4);
        Qs[c4 + 0][r] = v.x;
        Qs[c4 + 1][r] = v.y;
        Qs[c4 + 2][r] = v.z;
        Qs[c4 + 3][r] = v.w;
    }
    if (tid < BM) Zs[tid] = EPSF;
    __syncthreads();

    float yacc[4][4] = {};
    float zacc[4]    = {};

    for (int kt = 0; kt <= qt; kt++) {
        const int kbase = kt * BN;

        // ---- load K (transposed) and V tiles ----
        for (int i = tid; i < BN * (D_ / 4); i += 256) {
            int r  = i >> 4;
            int c4 = (i & 15) * 4;
            float4 kv = *(const float4*)(Kg + headoff + (size_t)(kbase + r) * rowstride + c4);
            Ks[c4 + 0][r] = kv.x;
            Ks[c4 + 1][r] = kv.y;
            Ks[c4 + 2][r] = kv.z;
            Ks[c4 + 3][r] = kv.w;
            *(float4*)&Vs[r][c4] =
                *(const float4*)(Vg + headoff + (size_t)(kbase + r) * rowstride + c4);
        }
        __syncthreads();

        // ---- GEMM1: S[q][k] = sum_d Q[q][d] * K[k][d] ----
        float sacc[4][4] = {};
        #pragma unroll 8
        for (int dd = 0; dd < D_; dd++) {
            float4 qv = *(const float4*)&Qs[dd][q0];
            float4 kv = *(const float4*)&Ks[dd][c0];
            float qa[4] = {qv.x, qv.y, qv.z, qv.w};
            float ka[4] = {kv.x, kv.y, kv.z, kv.w};
            #pragma unroll
            for (int i = 0; i < 4; i++)
                #pragma unroll
                for (int j = 0; j < 4; j++)
                    sacc[i][j] = fmaf(qa[i], ka[j], sacc[i][j]);
        }

        // ---- square + causal mask (diagonal tile only) + rowsum, store P ----
        const bool diag = (kt == qt);
        #pragma unroll
        for (int i = 0; i < 4; i++) {
            float4 prow;
            float* pr = (float*)&prow;
            #pragma unroll
            for (int j = 0; j < 4; j++) {
                float sv = sacc[i][j];
                sv = sv * sv;
                if (diag && (c0 + j > q0 + i)) sv = 0.0f;
                pr[j] = sv;
                zacc[i] += sv;
            }
            *(float4*)&Ss[q0 + i][c0] = prow;
        }
        __syncthreads();

        // ---- GEMM2: Y[q][v] += sum_k P[q][k] * V[k][v] ----
        #pragma unroll 4
        for (int kk = 0; kk < BN; kk += 4) {
            float4 sv0 = *(const float4*)&Ss[q0 + 0][kk];
            float4 sv1 = *(const float4*)&Ss[q0 + 1][kk];
            float4 sv2 = *(const float4*)&Ss[q0 + 2][kk];
            float4 sv3 = *(const float4*)&Ss[q0 + 3][kk];
            float sa[4][4] = {{sv0.x, sv0.y, sv0.z, sv0.w},
                              {sv1.x, sv1.y, sv1.z, sv1.w},
                              {sv2.x, sv2.y, sv2.z, sv2.w},
                              {sv3.x, sv3.y, sv3.z, sv3.w}};
            #pragma unroll
            for (int u = 0; u < 4; u++) {
                float4 vv = *(const float4*)&Vs[kk + u][c0];
                float va[4] = {vv.x, vv.y, vv.z, vv.w};
                #pragma unroll
                for (int i = 0; i < 4; i++)
                    #pragma unroll
                    for (int j = 0; j < 4; j++)
                        yacc[i][j] = fmaf(sa[i][u], va[j], yacc[i][j]);
            }
        }
        __syncthreads();
    }

    // ---- reduce Z across the 16 thread-columns ----
    #pragma unroll
    for (int i = 0; i < 4; i++) atomicAdd(&Zs[q0 + i], zacc[i]);
    __syncthreads();

    // ---- write output: O = Y / Z ----
    #pragma unroll
    for (int i = 0; i < 4; i++) {
        float inv = 1.0f / Zs[q0 + i];
        float4 o;
        o.x = yacc[i][0] * inv;
        o.y = yacc[i][1] * inv;
        o.z = yacc[i][2] * inv;
        o.w = yacc[i][3] * inv;
        *(float4*)(Og + headoff + (size_t)(qbase + q0 + i) * rowstride + c0) = o;
    }
}

extern "C" void kernel_launch(void* const* d_in, const int* in_sizes, int n_in,
                              void* d_out, int out_size)
{
    const float* Q = (const float*)d_in[0];
    const float* K = (const float*)d_in[1];
    const float* V = (const float*)d_in[2];
    // d_in[3] = chunk_count (unused: chunked form collapses to causal attention)
    float* O = (float*)d_out;

    dim3 grid(T_ / BM, B_ * H_);
    dim3 block(256);
    attn_pow2_kernel<<<grid, block>>>(Q, K, V, O);
}

// round 2
// speedup vs baseline: 1.2558x; 1.2558x over previous
#include <cuda_runtime.h>

// out[q] = sum_{k<=q} (Q_q.K_k)^2 V_k / (sum_{k<=q} (Q_q.K_k)^2 + EPS)
// b=2, t=2048, h=8, d=dv=64.  BM=BN=128 tiles, 8x8 micro-tiles, f32x2 packed FMA.

typedef unsigned long long u64;

constexpr int T_ = 2048;
constexpr int ROWSTRIDE = 512;     // h*d floats between consecutive tokens
constexpr float EPSF = 1e-5f;

// dynamic smem layout (float offsets)
constexpr int QS_OFF = 0;          // Qs[64][128]  (transposed, swizzled)
constexpr int KS_OFF = 8192;       // Ks[64][128]  (transposed, swizzled)
constexpr int VS_OFF = 16384;      // Vs[128][64]
constexpr int ST_OFF = 24576;      // St[128][128] (P transposed [k][q], swizzled)
constexpr int ZS_OFF = 40960;      // Zs[128]
constexpr size_t SMEM_BYTES = (size_t)41088 * 4;   // 164352 B

__device__ __forceinline__ u64 pk2(float x) {
    u64 r; asm("mov.b64 %0, {%1, %1};" : "=l"(r) : "f"(x)); return r;
}
__device__ __forceinline__ u64 ffma2(u64 a, u64 b, u64 c) {
    u64 d; asm("fma.rn.f32x2 %0, %1, %2, %3;" : "=l"(d) : "l"(a), "l"(b), "l"(c)); return d;
}
__device__ __forceinline__ u64 fmul2(u64 a, u64 b) {
    u64 d; asm("mul.rn.f32x2 %0, %1, %2;" : "=l"(d) : "l"(a), "l"(b)); return d;
}
__device__ __forceinline__ u64 fadd2(u64 a, u64 b) {
    u64 d; asm("add.rn.f32x2 %0, %1, %2;" : "=l"(d) : "l"(a), "l"(b)); return d;
}
__device__ __forceinline__ float2 up2(u64 a) {
    float2 f; asm("mov.b64 {%0, %1}, %2;" : "=f"(f.x), "=f"(f.y) : "l"(a)); return f;
}
__device__ __forceinline__ u64 pk(float x, float y) {
    u64 r; asm("mov.b64 %0, {%1, %2};" : "=l"(r) : "f"(x), "f"(y)); return r;
}

__global__ __launch_bounds__(256, 1)
void attn_pow2_kernel(const float* __restrict__ Qg,
                      const float* __restrict__ Kg,
                      const float* __restrict__ Vg,
                      float* __restrict__ Og)
{
    extern __shared__ float sm[];
    float* Qs = sm + QS_OFF;
    float* Ks = sm + KS_OFF;
    float* Vs = sm + VS_OFF;
    float* St = sm + ST_OFF;
    float* Zs = sm + ZS_OFF;

    const int qt  = (int)(gridDim.x - 1 - blockIdx.x);   // heavy tiles first
    const int bh  = (int)blockIdx.y;
    const int tid = (int)threadIdx.x;
    const int tx  = tid & 15;
    const int ty  = tid >> 4;
    const int q0  = ty * 8;     // 8 query rows (4 pairs)
    const int c0  = tx * 8;     // 8 key cols (GEMM1)
    const int v0  = tx * 4;     // 4 value cols (GEMM2)

    const size_t headoff = (size_t)(bh >> 3) * T_ * ROWSTRIDE + (size_t)(bh & 7) * 64;
    const int qbase = qt * 128;

    // ---- load Q tile: transpose into Qs[d][q^swz] ----
    #pragma unroll
    for (int it = 0; it < 8; it++) {
        int i  = tid + it * 256;
        int r  = i >> 4;
        int c4 = (i & 15) << 2;
        float4 v = *(const float4*)(Qg + headoff + (size_t)(qbase + r) * ROWSTRIDE + c4);
        int s  = ((c4 >> 3) & 7) << 2;
        int rs = r ^ s;
        Qs[(c4 + 0) * 128 + rs] = v.x;
        Qs[(c4 + 1) * 128 + rs] = v.y;
        Qs[(c4 + 2) * 128 + rs] = v.z;
        Qs[(c4 + 3) * 128 + rs] = v.w;
    }
    if (tid < 128) Zs[tid] = EPSF;

    u64 yacc[4][4] = {};
    u64 zacc[4]    = {};

    for (int kt = 0; kt <= qt; kt++) {
        const int kbase = kt * 128;
        __syncthreads();   // previous iteration done with Ks/Vs/St

        // ---- load K (transposed+swizzled) and V tiles ----
        #pragma unroll
        for (int it = 0; it < 8; it++) {
            int i  = tid + it * 256;
            int r  = i >> 4;
            int c4 = (i & 15) << 2;
            const float* gK = Kg + headoff + (size_t)(kbase + r) * ROWSTRIDE + c4;
            const float* gV = Vg + headoff + (size_t)(kbase + r) * ROWSTRIDE + c4;
            float4 kv = *(const float4*)gK;
            float4 vv = *(const float4*)gV;
            int s  = ((c4 >> 3) & 7) << 2;
            int rs = r ^ s;
            Ks[(c4 + 0) * 128 + rs] = kv.x;
            Ks[(c4 + 1) * 128 + rs] = kv.y;
            Ks[(c4 + 2) * 128 + rs] = kv.z;
            Ks[(c4 + 3) * 128 + rs] = kv.w;
            *(float4*)(Vs + r * 64 + c4) = vv;
        }
        __syncthreads();

        // ---- GEMM1: S[q][k] = sum_d Q[q][d]*K[k][d], pairs along q ----
        u64 sacc[4][8] = {};
        #pragma unroll 8
        for (int dd = 0; dd < 64; dd++) {
            const float* Qrow = Qs + dd * 128;
            const float* Krow = Ks + dd * 128;
            int s = ((dd >> 3) & 7) << 2;
            ulonglong2 qa = *(const ulonglong2*)(Qrow + (q0 ^ s));
            ulonglong2 qb = *(const ulonglong2*)(Qrow + ((q0 ^ s) ^ 4));
            float4 k0 = *(const float4*)(Krow + (c0 ^ s));
            float4 k1 = *(const float4*)(Krow + ((c0 ^ s) ^ 4));
            u64 kd[8];
            kd[0] = pk2(k0.x); kd[1] = pk2(k0.y); kd[2] = pk2(k0.z); kd[3] = pk2(k0.w);
            kd[4] = pk2(k1.x); kd[5] = pk2(k1.y); kd[6] = pk2(k1.z); kd[7] = pk2(k1.w);
            #pragma unroll
            for (int j = 0; j < 8; j++) {
                sacc[0][j] = ffma2(qa.x, kd[j], sacc[0][j]);
                sacc[1][j] = ffma2(qa.y, kd[j], sacc[1][j]);
                sacc[2][j] = ffma2(qb.x, kd[j], sacc[2][j]);
                sacc[3][j] = ffma2(qb.y, kd[j], sacc[3][j]);
            }
        }

        // ---- square, causal mask (diag tile), Z rowsum, store P transposed ----
        const bool diag = (kt == qt);
        const int  sj   = (tx & 7) << 2;          // ((c0+j)>>3)&7 == tx&7 for j<8
        #pragma unroll
        for (int j = 0; j < 8; j++) {
            u64 p2[4];
            #pragma unroll
            for (int i2 = 0; i2 < 4; i2++) {
                u64 p = fmul2(sacc[i2][j], sacc[i2][j]);
                if (diag) {
                    int col  = c0 + j;
                    int row0 = q0 + 2 * i2;
                    float2 f = up2(p);
                    if (col > row0)     f.x = 0.0f;
                    if (col > row0 + 1) f.y = 0.0f;
                    p = pk(f.x, f.y);
                }
                zacc[i2] = fadd2(zacc[i2], p);
                p2[i2] = p;
            }
            float* Srow = St + (c0 + j) * 128;
            *(ulonglong2*)(Srow + (q0 ^ sj))       = make_ulonglong2(p2[0], p2[1]);
            *(ulonglong2*)(Srow + ((q0 ^ sj) ^ 4)) = make_ulonglong2(p2[2], p2[3]);
        }
        __syncthreads();

        // ---- GEMM2: Y[q][v] += sum_k P[q][k]*V[k][v], pairs along q ----
        #pragma unroll 4
        for (int kk = 0; kk < 128; kk++) {
            int s = ((kk >> 3) & 7) << 2;
            const float* Srow = St + kk * 128;
            ulonglong2 pA = *(const ulonglong2*)(Srow + (q0 ^ s));
            ulonglong2 pB = *(const ulonglong2*)(Srow + ((q0 ^ s) ^ 4));
            float4 vv = *(const float4*)(Vs + kk * 64 + v0);
            u64 vd0 = pk2(vv.x), vd1 = pk2(vv.y), vd2 = pk2(vv.z), vd3 = pk2(vv.w);
            yacc[0][0] = ffma2(pA.x, vd0, yacc[0][0]);
            yacc[0][1] = ffma2(pA.x, vd1, yacc[0][1]);
            yacc[0][2] = ffma2(pA.x, vd2, yacc[0][2]);
            yacc[0][3] = ffma2(pA.x, vd3, yacc[0][3]);
            yacc[1][0] = ffma2(pA.y, vd0, yacc[1][0]);
            yacc[1][1] = ffma2(pA.y, vd1, yacc[1][1]);
            yacc[1][2] = ffma2(pA.y, vd2, yacc[1][2]);
            yacc[1][3] = ffma2(pA.y, vd3, yacc[1][3]);
            yacc[2][0] = ffma2(pB.x, vd0, yacc[2][0]);
            yacc[2][1] = ffma2(pB.x, vd1, yacc[2][1]);
            yacc[2][2] = ffma2(pB.x, vd2, yacc[2][2]);
            yacc[2][3] = ffma2(pB.x, vd3, yacc[2][3]);
            yacc[3][0] = ffma2(pB.y, vd0, yacc[3][0]);
            yacc[3][1] = ffma2(pB.y, vd1, yacc[3][1]);
            yacc[3][2] = ffma2(pB.y, vd2, yacc[3][2]);
            yacc[3][3] = ffma2(pB.y, vd3, yacc[3][3]);
        }
    }

    // ---- reduce Z across thread columns ----
    #pragma unroll
    for (int i2 = 0; i2 < 4; i2++) {
        float2 z = up2(zacc[i2]);
        atomicAdd(&Zs[q0 + 2 * i2],     z.x);
        atomicAdd(&Zs[q0 + 2 * i2 + 1], z.y);
    }
    __syncthreads();

    // ---- write O = Y / Z ----
    #pragma unroll
    for (int i2 = 0; i2 < 4; i2++) {
        int r0 = q0 + 2 * i2;
        float ie = 1.0f / Zs[r0];
        float io = 1.0f / Zs[r0 + 1];
        float4 oe, oo;
        float2 y0 = up2(yacc[i2][0]);
        float2 y1 = up2(yacc[i2][1]);
        float2 y2 = up2(yacc[i2][2]);
        float2 y3 = up2(yacc[i2][3]);
        oe.x = y0.x * ie; oe.y = y1.x * ie; oe.z = y2.x * ie; oe.w = y3.x * ie;
        oo.x = y0.y * io; oo.y = y1.y * io; oo.z = y2.y * io; oo.w = y3.y * io;
        *(float4*)(Og + headoff + (size_t)(qbase + r0)     * ROWSTRIDE + v0) = oe;
        *(float4*)(Og + headoff + (size_t)(qbase + r0 + 1) * ROWSTRIDE + v0) = oo;
    }
}

extern "C" void kernel_launch(void* const* d_in, const int* in_sizes, int n_in,
                              void* d_out, int out_size)
{
    const float* Q = (const float*)d_in[0];
    const float* K = (const float*)d_in[1];
    const float* V = (const float*)d_in[2];
    float* O = (float*)d_out;

    cudaFuncSetAttribute(attn_pow2_kernel,
                         cudaFuncAttributeMaxDynamicSharedMemorySize,
                         (int)SMEM_BYTES);

    dim3 grid(T_ / 128, 16);
    dim3 block(256);
    attn_pow2_kernel<<<grid, block, SMEM_BYTES>>>(Q, K, V, O);
}